// round 1
// baseline (speedup 1.0000x reference)
#include <cuda_runtime.h>
#include <math.h>

#define EMBED   1024
#define NH      8
#define HD      128
#define MAXDIST 128
#define RADIUS_ 256
#define RR      257     // 2*MAXDIST+1
#define B_      4
#define S_      1024
#define BHN     (B_*NH) // 32

// ---------------- scratch (device globals; no allocs allowed) ----------------
__device__ float g_Qp[BHN * S_ * HD];      // 16 MB
__device__ float g_Kp[BHN * S_ * HD];      // 16 MB
__device__ float g_Vp[BHN * S_ * HD];      // 16 MB
__device__ float g_ctx[B_ * S_ * EMBED];   // 16 MB, stored with f = d*NH + h

// ---------------- generic SGEMM: C = A(MxK) * B(NxK)^T ----------------
// MODE 0: scatter epilogue into [bh, s, d] projection layout
// MODE 1: plain row-major C[m*N+n]
template<int MODE>
__global__ __launch_bounds__(256) void sgemm_abt(
    const float* __restrict__ A, const float* __restrict__ Bm,
    float* __restrict__ C, int M, int N, int K)
{
    __shared__ float As[16][132];
    __shared__ float Bs[16][132];

    const int m0 = blockIdx.y * 128;
    const int n0 = blockIdx.x * 128;
    const int tid = threadIdx.x;
    const int tx = tid & 15;       // col group
    const int ty = tid >> 4;       // row group

    float acc[8][8];
    #pragma unroll
    for (int i = 0; i < 8; i++)
        #pragma unroll
        for (int j = 0; j < 8; j++) acc[i][j] = 0.f;

    for (int k0 = 0; k0 < K; k0 += 16) {
        #pragma unroll
        for (int p = 0; p < 2; p++) {
            int idx = tid + p * 256;         // 512 float4 loads per operand
            int row = idx >> 2;
            int kq  = (idx & 3) << 2;
            float4 a = *(const float4*)&A[(size_t)(m0 + row) * K + k0 + kq];
            As[kq + 0][row] = a.x; As[kq + 1][row] = a.y;
            As[kq + 2][row] = a.z; As[kq + 3][row] = a.w;
            float4 b = *(const float4*)&Bm[(size_t)(n0 + row) * K + k0 + kq];
            Bs[kq + 0][row] = b.x; Bs[kq + 1][row] = b.y;
            Bs[kq + 2][row] = b.z; Bs[kq + 3][row] = b.w;
        }
        __syncthreads();

        #pragma unroll
        for (int kk = 0; kk < 16; kk++) {
            float a[8], b[8];
            *(float4*)&a[0] = *(float4*)&As[kk][ty * 8];
            *(float4*)&a[4] = *(float4*)&As[kk][ty * 8 + 4];
            *(float4*)&b[0] = *(float4*)&Bs[kk][tx * 8];
            *(float4*)&b[4] = *(float4*)&Bs[kk][tx * 8 + 4];
            #pragma unroll
            for (int i = 0; i < 8; i++)
                #pragma unroll
                for (int j = 0; j < 8; j++)
                    acc[i][j] += a[i] * b[j];
        }
        __syncthreads();
    }

    #pragma unroll
    for (int i = 0; i < 8; i++) {
        int m = m0 + ty * 8 + i;
        #pragma unroll
        for (int j = 0; j < 8; j++) {
            int n = n0 + tx * 8 + j;
            if (MODE == 0) {
                // y[b,s,e] -> P[(b*NH+h), s, d], e = h*HD + d
                int b = m >> 10, s = m & 1023;
                int h = n >> 7,  d = n & 127;
                C[(((size_t)(b * NH + h)) * S_ + s) * HD + d] = acc[i][j];
            } else {
                C[(size_t)m * N + n] = acc[i][j];
            }
        }
    }
}

// ---------------- banded relative attention ----------------
// grid = (Sq/32, B*NH), 256 threads
// smem layout (floats):
//   sQ    [32][129]  off 0      (4128)
//   sQrel [32][260]  off 4128   (8320)
//   sS    [32][545]  off 12448  (17440)   band = 544 cols
//   sKV   [64][132]  off 29888  (8448)    K/rel tiles use stride 129, V uses 132
#define SM_Q     0
#define SM_QREL  4128
#define SM_S     12448
#define SM_KV    29888
#define SM_FLOATS 38336   // 153344 bytes

__global__ __launch_bounds__(256) void attn_kernel(
    const float* __restrict__ Qp, const float* __restrict__ Kp,
    const float* __restrict__ Vp, const float* __restrict__ rel,
    const unsigned char* __restrict__ pad, float* __restrict__ ctx)
{
    constexpr int QT = 32, KT = 64, BAND = 2 * RADIUS_ + QT;   // 544

    extern __shared__ float sm[];
    float* sQ    = sm + SM_Q;
    float* sQrel = sm + SM_QREL;
    float* sS    = sm + SM_S;
    float* sKV   = sm + SM_KV;

    const int tid = threadIdx.x;
    const int bh  = blockIdx.y;
    const int b   = bh >> 3;
    const int h   = bh & 7;
    const int q0  = blockIdx.x * QT;
    const int kbase = q0 - RADIUS_;

    const float* Qb   = Qp  + (size_t)bh * S_ * HD;
    const float* Kb   = Kp  + (size_t)bh * S_ * HD;
    const float* Vb   = Vp  + (size_t)bh * S_ * HD;
    const float* relh = rel + (size_t)h * RR * HD;

    // ---- load Q tile ----
    for (int idx = tid; idx < QT * HD; idx += 256) {
        int q = idx >> 7, d = idx & 127;
        sQ[q * 129 + d] = Qb[(size_t)(q0 + q) * HD + d];
    }
    __syncthreads();

    const int tx = tid & 15, ty = tid >> 4;
    const int k0l = tx * 4, q0l = ty * 2;

    // ---- Q_rel[q][r] = Qp[q] . rel_emb[h][r], r in [0,257) ----
    for (int rt = 0; rt < 5; rt++) {
        for (int idx = tid; idx < KT * HD; idx += 256) {
            int r = idx >> 7, d = idx & 127;
            int rg = rt * KT + r;
            sKV[r * 129 + d] = (rg < RR) ? relh[(size_t)rg * HD + d] : 0.f;
        }
        __syncthreads();
        float acc[2][4] = {{0.f,0.f,0.f,0.f},{0.f,0.f,0.f,0.f}};
        #pragma unroll 8
        for (int d = 0; d < HD; d++) {
            float a0 = sQ[q0l * 129 + d];
            float a1 = sQ[(q0l + 1) * 129 + d];
            #pragma unroll
            for (int j = 0; j < 4; j++) {
                float bb = sKV[(k0l + j) * 129 + d];
                acc[0][j] += a0 * bb;
                acc[1][j] += a1 * bb;
            }
        }
        #pragma unroll
        for (int i = 0; i < 2; i++)
            #pragma unroll
            for (int j = 0; j < 4; j++) {
                int rg = rt * KT + k0l + j;
                if (rg < RR) sQrel[(q0l + i) * 260 + rg] = acc[i][j];
            }
        __syncthreads();
    }

    // ---- raw scores over band ----
    for (int kt = 0; kt < 9; kt++) {
        for (int idx = tid; idx < KT * HD; idx += 256) {
            int r = idx >> 7, d = idx & 127;
            int k = kbase + kt * KT + r;
            sKV[r * 129 + d] = (k >= 0 && k < S_) ? Kb[(size_t)k * HD + d] : 0.f;
        }
        __syncthreads();
        float acc[2][4] = {{0.f,0.f,0.f,0.f},{0.f,0.f,0.f,0.f}};
        #pragma unroll 8
        for (int d = 0; d < HD; d++) {
            float a0 = sQ[q0l * 129 + d];
            float a1 = sQ[(q0l + 1) * 129 + d];
            #pragma unroll
            for (int j = 0; j < 4; j++) {
                float bb = sKV[(k0l + j) * 129 + d];
                acc[0][j] += a0 * bb;
                acc[1][j] += a1 * bb;
            }
        }
        #pragma unroll
        for (int i = 0; i < 2; i++)
            #pragma unroll
            for (int j = 0; j < 4; j++) {
                int kk = kt * KT + k0l + j;
                if (kk < BAND) sS[(q0l + i) * 545 + kk] = acc[i][j];
            }
        __syncthreads();
    }

    // ---- energy = (score + rel_shift)/sqrt(D), apply masks ----
    const float scale = 0.08838834764831845f;   // 1/sqrt(128)
    for (int idx = tid; idx < QT * BAND; idx += 256) {
        int q = idx / BAND, kk = idx - q * BAND;
        int k = kbase + kk;
        int qg = q0 + q;
        int dlt = k - qg;
        float v = -INFINITY;
        if (k >= 0 && k < S_ && dlt <= RADIUS_ && dlt >= -RADIUS_ &&
            pad[b * S_ + k] == 0) {
            int rid = dlt;
            rid = (rid >  MAXDIST) ?  MAXDIST : rid;
            rid = (rid < -MAXDIST) ? -MAXDIST : rid;
            rid += MAXDIST;
            v = (sS[q * 545 + kk] + sQrel[q * 260 + rid]) * scale;
        }
        sS[q * 545 + kk] = v;
    }
    __syncthreads();

    // ---- row softmax (each warp owns 4 rows) ----
    {
        int w = tid >> 5, lane = tid & 31;
        for (int rr = 0; rr < 4; rr++) {
            float* row = sS + (w * 4 + rr) * 545;
            float m = -INFINITY;
            for (int kk = lane; kk < BAND; kk += 32) m = fmaxf(m, row[kk]);
            #pragma unroll
            for (int o = 16; o > 0; o >>= 1)
                m = fmaxf(m, __shfl_xor_sync(0xffffffffu, m, o));
            float s = 0.f;
            for (int kk = lane; kk < BAND; kk += 32) {
                float e = __expf(row[kk] - m);
                row[kk] = e;
                s += e;
            }
            #pragma unroll
            for (int o = 16; o > 0; o >>= 1)
                s += __shfl_xor_sync(0xffffffffu, s, o);
            float inv = 1.f / s;
            for (int kk = lane; kk < BAND; kk += 32) row[kk] *= inv;
        }
    }
    __syncthreads();

    // ---- out = P @ V ----
    const int d0 = (tid & 31) * 4;
    const int ql = (tid >> 5) * 4;
    float o[4][4];
    #pragma unroll
    for (int i = 0; i < 4; i++)
        #pragma unroll
        for (int j = 0; j < 4; j++) o[i][j] = 0.f;

    for (int kt = 0; kt < 9; kt++) {
        for (int idx = tid; idx < KT * HD; idx += 256) {
            int r = idx >> 7, d = idx & 127;
            int k = kbase + kt * KT + r;
            sKV[r * 132 + d] = (k >= 0 && k < S_) ? Vb[(size_t)k * HD + d] : 0.f;
        }
        __syncthreads();
        int tw = BAND - kt * KT; if (tw > KT) tw = KT;
        for (int kkl = 0; kkl < tw; kkl++) {
            float4 v4 = *(float4*)&sKV[kkl * 132 + d0];
            int kk = kt * KT + kkl;
            float p0 = sS[(ql + 0) * 545 + kk];
            float p1 = sS[(ql + 1) * 545 + kk];
            float p2 = sS[(ql + 2) * 545 + kk];
            float p3 = sS[(ql + 3) * 545 + kk];
            o[0][0] += p0 * v4.x; o[0][1] += p0 * v4.y; o[0][2] += p0 * v4.z; o[0][3] += p0 * v4.w;
            o[1][0] += p1 * v4.x; o[1][1] += p1 * v4.y; o[1][2] += p1 * v4.z; o[1][3] += p1 * v4.w;
            o[2][0] += p2 * v4.x; o[2][1] += p2 * v4.y; o[2][2] += p2 * v4.z; o[2][3] += p2 * v4.w;
            o[3][0] += p3 * v4.x; o[3][1] += p3 * v4.y; o[3][2] += p3 * v4.z; o[3][3] += p3 * v4.w;
        }
        __syncthreads();
    }

    // ---- write ctx with permuted feature index f = d*NH + h ----
    #pragma unroll
    for (int i = 0; i < 4; i++) {
        int q = q0 + ql + i;
        #pragma unroll
        for (int j = 0; j < 4; j++) {
            int d = d0 + j;
            ctx[((size_t)(b * S_ + q)) * EMBED + d * NH + h] = o[i][j];
        }
    }
}

// ---------------- launcher ----------------
extern "C" void kernel_launch(void* const* d_in, const int* in_sizes, int n_in,
                              void* d_out, int out_size)
{
    const float*         Q   = (const float*)d_in[0];
    const float*         K   = (const float*)d_in[1];
    const float*         V   = (const float*)d_in[2];
    /* d_in[3] = segment_ids (unused by reference) */
    const unsigned char* pad = (const unsigned char*)d_in[4];
    const float*         Wq  = (const float*)d_in[5];
    const float*         Wk  = (const float*)d_in[6];
    const float*         Wv  = (const float*)d_in[7];
    const float*         Wo  = (const float*)d_in[8];
    const float*         rel = (const float*)d_in[9];
    float*               out = (float*)d_out;

    float *Qp, *Kp, *Vp, *ctx;
    cudaGetSymbolAddress((void**)&Qp,  g_Qp);
    cudaGetSymbolAddress((void**)&Kp,  g_Kp);
    cudaGetSymbolAddress((void**)&Vp,  g_Vp);
    cudaGetSymbolAddress((void**)&ctx, g_ctx);

    dim3 gg(EMBED / 128, (B_ * S_) / 128);   // (8, 32)

    sgemm_abt<0><<<gg, 256>>>(Q, Wq, Qp, B_ * S_, EMBED, EMBED);
    sgemm_abt<0><<<gg, 256>>>(K, Wk, Kp, B_ * S_, EMBED, EMBED);
    sgemm_abt<0><<<gg, 256>>>(V, Wv, Vp, B_ * S_, EMBED, EMBED);

    cudaFuncSetAttribute(attn_kernel,
                         cudaFuncAttributeMaxDynamicSharedMemorySize,
                         SM_FLOATS * 4);
    attn_kernel<<<dim3(S_ / 32, BHN), 256, SM_FLOATS * 4>>>(Qp, Kp, Vp, rel, pad, ctx);

    sgemm_abt<1><<<gg, 256>>>(ctx, Wo, out, B_ * S_, EMBED, EMBED);
}

// round 2
// speedup vs baseline: 1.1229x; 1.1229x over previous
#include <cuda_runtime.h>
#include <math.h>

#define EMBED   1024
#define NH      8
#define HD      128
#define MAXDIST 128
#define RADIUS_ 256
#define RR      257
#define B_      4
#define S_      1024
#define BHN     32
#define BAND    640     // 5*128 k-tiles covering band width 576 (QT=64)

// ---------------- scratch ----------------
__device__ float g_Qp[BHN * S_ * HD];
__device__ float g_Kp[BHN * S_ * HD];
__device__ float g_Vp[BHN * S_ * HD];
__device__ float g_Qrel[BHN * S_ * RR];
__device__ float g_S[(size_t)BHN * S_ * BAND];   // 84 MB band scores
__device__ float g_ctx[B_ * S_ * EMBED];         // standard layout [b][s][h*128+d]
__device__ float g_Wop[EMBED * EMBED];           // permuted Wo

// ---------------- fast exp (FMA-only, x <= 0) ----------------
__device__ __forceinline__ float fexp(float x) {
    float z = x * 1.4426950408889634f;
    z = fmaxf(z, -127.0f);                 // also handles -inf
    float n = rintf(z);
    float f = z - n;
    float p =           1.3333558e-3f;
    p = fmaf(p, f, 9.6181290e-3f);
    p = fmaf(p, f, 5.5504109e-2f);
    p = fmaf(p, f, 2.4022651e-1f);
    p = fmaf(p, f, 6.9314718e-1f);
    p = fmaf(p, f, 1.0f);
    float sc = __int_as_float(((int)n + 127) << 23);
    return p * sc;
}

// ---------------- big SGEMM: C = A(Mx1024) * B(Nx1024)^T, double-buffered ----------------
// MODE 0: scatter into projection layout [bh][s][d]; MODE 1: plain row-major
template<int MODE>
__global__ __launch_bounds__(256) void sgemm128(
    const float* __restrict__ A, const float* __restrict__ Bm, float* __restrict__ C)
{
    extern __shared__ float sm[];
    float (*As)[16][132] = (float(*)[16][132])sm;
    float (*Bs)[16][132] = (float(*)[16][132])(sm + 2 * 16 * 132);

    const int m0 = blockIdx.y * 128;
    const int n0 = blockIdx.x * 128;
    const int tid = threadIdx.x;
    const int tx = tid & 15, ty = tid >> 4;
    const int lrow = tid >> 2;
    const int lkq  = (tid & 3) << 2;

    float acc[8][8];
    #pragma unroll
    for (int i = 0; i < 8; i++)
        #pragma unroll
        for (int j = 0; j < 8; j++) acc[i][j] = 0.f;

    float4 pa0, pa1, pb0, pb1;
    // preload slab 0
    pa0 = *(const float4*)&A[(size_t)(m0 + lrow) * 1024 + lkq];
    pa1 = *(const float4*)&A[(size_t)(m0 + lrow + 64) * 1024 + lkq];
    pb0 = *(const float4*)&Bm[(size_t)(n0 + lrow) * 1024 + lkq];
    pb1 = *(const float4*)&Bm[(size_t)(n0 + lrow + 64) * 1024 + lkq];
    {
        As[0][lkq+0][lrow] = pa0.x; As[0][lkq+1][lrow] = pa0.y; As[0][lkq+2][lrow] = pa0.z; As[0][lkq+3][lrow] = pa0.w;
        As[0][lkq+0][lrow+64] = pa1.x; As[0][lkq+1][lrow+64] = pa1.y; As[0][lkq+2][lrow+64] = pa1.z; As[0][lkq+3][lrow+64] = pa1.w;
        Bs[0][lkq+0][lrow] = pb0.x; Bs[0][lkq+1][lrow] = pb0.y; Bs[0][lkq+2][lrow] = pb0.z; Bs[0][lkq+3][lrow] = pb0.w;
        Bs[0][lkq+0][lrow+64] = pb1.x; Bs[0][lkq+1][lrow+64] = pb1.y; Bs[0][lkq+2][lrow+64] = pb1.z; Bs[0][lkq+3][lrow+64] = pb1.w;
    }
    __syncthreads();

    for (int s = 0; s < 64; s++) {
        const int cur = s & 1;
        if (s < 63) {
            int k0 = (s + 1) * 16;
            pa0 = *(const float4*)&A[(size_t)(m0 + lrow) * 1024 + k0 + lkq];
            pa1 = *(const float4*)&A[(size_t)(m0 + lrow + 64) * 1024 + k0 + lkq];
            pb0 = *(const float4*)&Bm[(size_t)(n0 + lrow) * 1024 + k0 + lkq];
            pb1 = *(const float4*)&Bm[(size_t)(n0 + lrow + 64) * 1024 + k0 + lkq];
        }
        #pragma unroll
        for (int kk = 0; kk < 16; kk++) {
            float a[8], b[8];
            *(float4*)&a[0] = *(const float4*)&As[cur][kk][ty * 8];
            *(float4*)&a[4] = *(const float4*)&As[cur][kk][ty * 8 + 4];
            *(float4*)&b[0] = *(const float4*)&Bs[cur][kk][tx * 8];
            *(float4*)&b[4] = *(const float4*)&Bs[cur][kk][tx * 8 + 4];
            #pragma unroll
            for (int i = 0; i < 8; i++)
                #pragma unroll
                for (int j = 0; j < 8; j++)
                    acc[i][j] += a[i] * b[j];
        }
        if (s < 63) {
            const int nxt = cur ^ 1;
            As[nxt][lkq+0][lrow] = pa0.x; As[nxt][lkq+1][lrow] = pa0.y; As[nxt][lkq+2][lrow] = pa0.z; As[nxt][lkq+3][lrow] = pa0.w;
            As[nxt][lkq+0][lrow+64] = pa1.x; As[nxt][lkq+1][lrow+64] = pa1.y; As[nxt][lkq+2][lrow+64] = pa1.z; As[nxt][lkq+3][lrow+64] = pa1.w;
            Bs[nxt][lkq+0][lrow] = pb0.x; Bs[nxt][lkq+1][lrow] = pb0.y; Bs[nxt][lkq+2][lrow] = pb0.z; Bs[nxt][lkq+3][lrow] = pb0.w;
            Bs[nxt][lkq+0][lrow+64] = pb1.x; Bs[nxt][lkq+1][lrow+64] = pb1.y; Bs[nxt][lkq+2][lrow+64] = pb1.z; Bs[nxt][lkq+3][lrow+64] = pb1.w;
        }
        __syncthreads();
    }

    #pragma unroll
    for (int i = 0; i < 8; i++) {
        int m = m0 + ty * 8 + i;
        #pragma unroll
        for (int j = 0; j < 8; j++) {
            int n = n0 + tx * 8 + j;
            if (MODE == 0) {
                int b = m >> 10, s = m & 1023;
                int h = n >> 7,  d = n & 127;
                C[(((size_t)(b * NH + h)) * S_ + s) * HD + d] = acc[i][j];
            } else {
                C[(size_t)m * 1024 + n] = acc[i][j];
            }
        }
    }
}

// ---------------- Wo permute: g_Wop[n][h*128+d] = Wo[n][d*8+h] ----------------
__global__ void wo_permute(const float* __restrict__ Wo)
{
    int n = blockIdx.x;
    for (int f = threadIdx.x; f < 1024; f += 256) {
        int h = f >> 7, d = f & 127;
        g_Wop[n * 1024 + f] = Wo[n * 1024 + d * 8 + h];
    }
}

// ---------------- Qrel GEMM: g_Qrel[bh][q][r] = Qp[bh][q] . rel[h][r] ----------------
// grid (3 r-tiles, 16 q-tiles, 32 bh), 128 threads, tile 64q x 128r
__global__ __launch_bounds__(128) void qrel_gemm(const float* __restrict__ rel)
{
    __shared__ float As[2][16][68];
    __shared__ float Bs[2][16][128];

    const int tid = threadIdx.x;
    const int r0 = blockIdx.x * 128;
    const int q0 = blockIdx.y * 64;
    const int bh = blockIdx.z;
    const int h = bh & 7;
    const float* Aq = g_Qp + (size_t)bh * S_ * HD;
    const float* Br = rel + (size_t)h * RR * HD;

    const int tyq = tid >> 4, txn = tid & 15;
    float acc[8][8];
    #pragma unroll
    for (int i = 0; i < 8; i++)
        #pragma unroll
        for (int j = 0; j < 8; j++) acc[i][j] = 0.f;

    float4 pa[2], pb[4];
    auto ldg = [&](int k0) {
        #pragma unroll
        for (int p = 0; p < 2; p++) {
            int lin = tid + p * 128;
            int r = lin & 63, c4 = (lin >> 6) << 2;
            pa[p] = *(const float4*)&Aq[(size_t)(q0 + r) * HD + k0 + c4];
        }
        #pragma unroll
        for (int p = 0; p < 4; p++) {
            int lin = tid + p * 128;
            int r = lin & 127, c4 = (lin >> 7) << 2;
            int rg = r0 + r;
            pb[p] = (rg < RR) ? *(const float4*)&Br[(size_t)rg * HD + k0 + c4]
                              : make_float4(0.f, 0.f, 0.f, 0.f);
        }
    };
    auto sts = [&](int buf) {
        #pragma unroll
        for (int p = 0; p < 2; p++) {
            int lin = tid + p * 128;
            int r = lin & 63, c4 = (lin >> 6) << 2;
            As[buf][c4+0][r] = pa[p].x; As[buf][c4+1][r] = pa[p].y;
            As[buf][c4+2][r] = pa[p].z; As[buf][c4+3][r] = pa[p].w;
        }
        #pragma unroll
        for (int p = 0; p < 4; p++) {
            int lin = tid + p * 128;
            int r = lin & 127, c4 = (lin >> 7) << 2;
            Bs[buf][c4+0][r] = pb[p].x; Bs[buf][c4+1][r] = pb[p].y;
            Bs[buf][c4+2][r] = pb[p].z; Bs[buf][c4+3][r] = pb[p].w;
        }
    };

    ldg(0); sts(0); __syncthreads();
    for (int s = 0; s < 8; s++) {
        const int cur = s & 1;
        if (s < 7) ldg((s + 1) * 16);
        #pragma unroll
        for (int dd = 0; dd < 16; dd++) {
            float a[8], b[8];
            *(float4*)&a[0] = *(const float4*)&As[cur][dd][tyq * 8];
            *(float4*)&a[4] = *(const float4*)&As[cur][dd][tyq * 8 + 4];
            *(float4*)&b[0] = *(const float4*)&Bs[cur][dd][txn * 8];
            *(float4*)&b[4] = *(const float4*)&Bs[cur][dd][txn * 8 + 4];
            #pragma unroll
            for (int i = 0; i < 8; i++)
                #pragma unroll
                for (int j = 0; j < 8; j++)
                    acc[i][j] += a[i] * b[j];
        }
        if (s < 7) sts(cur ^ 1);
        __syncthreads();
    }

    #pragma unroll
    for (int i = 0; i < 8; i++) {
        size_t rowoff = ((size_t)bh * S_ + q0 + tyq * 8 + i) * RR;
        #pragma unroll
        for (int j = 0; j < 8; j++) {
            int rg = r0 + txn * 8 + j;
            if (rg < RR) g_Qrel[rowoff + rg] = acc[i][j];
        }
    }
}

// ---------------- banded scores: g_S[bh][q][kk] ----------------
// grid (5 k-tiles, 16 q-tiles, 32 bh), 128 threads, tile 64q x 128kk
__global__ __launch_bounds__(128) void score_kernel(const unsigned char* __restrict__ pad)
{
    __shared__ float As[2][16][68];
    __shared__ float Bs[2][16][128];

    const int tid = threadIdx.x;
    const int kt0 = blockIdx.x * 128;
    const int q0  = blockIdx.y * 64;
    const int bh  = blockIdx.z;
    const int b   = bh >> 3;
    const int kbase = q0 - RADIUS_;
    const float* Aq = g_Qp + (size_t)bh * S_ * HD;
    const float* Kb = g_Kp + (size_t)bh * S_ * HD;

    const int tyq = tid >> 4, txk = tid & 15;
    float acc[8][8];
    #pragma unroll
    for (int i = 0; i < 8; i++)
        #pragma unroll
        for (int j = 0; j < 8; j++) acc[i][j] = 0.f;

    float4 pa[2], pb[4];
    auto ldg = [&](int k0) {
        #pragma unroll
        for (int p = 0; p < 2; p++) {
            int lin = tid + p * 128;
            int r = lin & 63, c4 = (lin >> 6) << 2;
            pa[p] = *(const float4*)&Aq[(size_t)(q0 + r) * HD + k0 + c4];
        }
        #pragma unroll
        for (int p = 0; p < 4; p++) {
            int lin = tid + p * 128;
            int r = lin & 127, c4 = (lin >> 7) << 2;
            int k = kbase + kt0 + r;
            pb[p] = (k >= 0 && k < S_) ? *(const float4*)&Kb[(size_t)k * HD + k0 + c4]
                                       : make_float4(0.f, 0.f, 0.f, 0.f);
        }
    };
    auto sts = [&](int buf) {
        #pragma unroll
        for (int p = 0; p < 2; p++) {
            int lin = tid + p * 128;
            int r = lin & 63, c4 = (lin >> 6) << 2;
            As[buf][c4+0][r] = pa[p].x; As[buf][c4+1][r] = pa[p].y;
            As[buf][c4+2][r] = pa[p].z; As[buf][c4+3][r] = pa[p].w;
        }
        #pragma unroll
        for (int p = 0; p < 4; p++) {
            int lin = tid + p * 128;
            int r = lin & 127, c4 = (lin >> 7) << 2;
            Bs[buf][c4+0][r] = pb[p].x; Bs[buf][c4+1][r] = pb[p].y;
            Bs[buf][c4+2][r] = pb[p].z; Bs[buf][c4+3][r] = pb[p].w;
        }
    };

    ldg(0); sts(0); __syncthreads();
    for (int s = 0; s < 8; s++) {
        const int cur = s & 1;
        if (s < 7) ldg((s + 1) * 16);
        #pragma unroll
        for (int dd = 0; dd < 16; dd++) {
            float a[8], bb[8];
            *(float4*)&a[0] = *(const float4*)&As[cur][dd][tyq * 8];
            *(float4*)&a[4] = *(const float4*)&As[cur][dd][tyq * 8 + 4];
            *(float4*)&bb[0] = *(const float4*)&Bs[cur][dd][txk * 8];
            *(float4*)&bb[4] = *(const float4*)&Bs[cur][dd][txk * 8 + 4];
            #pragma unroll
            for (int i = 0; i < 8; i++)
                #pragma unroll
                for (int j = 0; j < 8; j++)
                    acc[i][j] += a[i] * bb[j];
        }
        if (s < 7) sts(cur ^ 1);
        __syncthreads();
    }

    const float scale = 0.08838834764831845f;
    #pragma unroll
    for (int i = 0; i < 8; i++) {
        int qg = q0 + tyq * 8 + i;
        size_t rbase = (size_t)bh * S_ + qg;
        #pragma unroll
        for (int j = 0; j < 8; j++) {
            int kk = kt0 + txk * 8 + j;
            int k = kbase + kk;
            int dlt = k - qg;
            float e = -INFINITY;
            if (k >= 0 && k < S_ && dlt >= -RADIUS_ && dlt <= RADIUS_ &&
                pad[b * S_ + k] == 0) {
                int rid = dlt;
                rid = rid < -MAXDIST ? -MAXDIST : (rid > MAXDIST ? MAXDIST : rid);
                rid += MAXDIST;
                e = (acc[i][j] + g_Qrel[rbase * RR + rid]) * scale;
            }
            g_S[rbase * BAND + kk] = e;
        }
    }
}

// ---------------- band softmax: one warp per row of 640 ----------------
__global__ __launch_bounds__(256) void softmax_band()
{
    int row  = blockIdx.x * 8 + (threadIdx.x >> 5);
    int lane = threadIdx.x & 31;
    float* Srow = g_S + (size_t)row * BAND;

    float4 v[5];
    #pragma unroll
    for (int p = 0; p < 5; p++) v[p] = *(const float4*)&Srow[p * 128 + lane * 4];

    float m = -INFINITY;
    #pragma unroll
    for (int p = 0; p < 5; p++) {
        m = fmaxf(m, fmaxf(fmaxf(v[p].x, v[p].y), fmaxf(v[p].z, v[p].w)));
    }
    #pragma unroll
    for (int o = 16; o > 0; o >>= 1) m = fmaxf(m, __shfl_xor_sync(0xffffffffu, m, o));

    float sum = 0.f;
    #pragma unroll
    for (int p = 0; p < 5; p++) {
        v[p].x = fexp(v[p].x - m); v[p].y = fexp(v[p].y - m);
        v[p].z = fexp(v[p].z - m); v[p].w = fexp(v[p].w - m);
        sum += v[p].x + v[p].y + v[p].z + v[p].w;
    }
    #pragma unroll
    for (int o = 16; o > 0; o >>= 1) sum += __shfl_xor_sync(0xffffffffu, sum, o);

    float inv = 1.f / sum;
    #pragma unroll
    for (int p = 0; p < 5; p++) {
        v[p].x *= inv; v[p].y *= inv; v[p].z *= inv; v[p].w *= inv;
        *(float4*)&Srow[p * 128 + lane * 4] = v[p];
    }
}

// ---------------- PV: ctx[b][s][h*128+d] = sum_kk P[q][kk] * V[kbase+kk][d] ----------------
// grid (16 q-tiles, 32 bh), 128 threads, tile 64q x 128d, contraction 640
__global__ __launch_bounds__(128) void pv_kernel()
{
    __shared__ float As[2][16][68];
    __shared__ float Vs[2][16][132];

    const int tid = threadIdx.x;
    const int q0 = blockIdx.x * 64;
    const int bh = blockIdx.y;
    const int b = bh >> 3, h = bh & 7;
    const int kbase = q0 - RADIUS_;
    const float* Vb = g_Vp + (size_t)bh * S_ * HD;

    const int tyq = tid >> 4, txd = tid & 15;
    float acc[8][8];
    #pragma unroll
    for (int i = 0; i < 8; i++)
        #pragma unroll
        for (int j = 0; j < 8; j++) acc[i][j] = 0.f;

    float4 pa[2], pv[4];
    auto ldg = [&](int k0) {
        #pragma unroll
        for (int p = 0; p < 2; p++) {
            int lin = tid + p * 128;
            int r = lin & 63, c4 = (lin >> 6) << 2;
            pa[p] = *(const float4*)&g_S[((size_t)bh * S_ + q0 + r) * BAND + k0 + c4];
        }
        #pragma unroll
        for (int p = 0; p < 4; p++) {
            int lin = tid + p * 128;
            int vr = lin >> 5, vd4 = (lin & 31) << 2;
            int k = kbase + k0 + vr;
            pv[p] = (k >= 0 && k < S_) ? *(const float4*)&Vb[(size_t)k * HD + vd4]
                                       : make_float4(0.f, 0.f, 0.f, 0.f);
        }
    };
    auto sts = [&](int buf) {
        #pragma unroll
        for (int p = 0; p < 2; p++) {
            int lin = tid + p * 128;
            int r = lin & 63, c4 = (lin >> 6) << 2;
            As[buf][c4+0][r] = pa[p].x; As[buf][c4+1][r] = pa[p].y;
            As[buf][c4+2][r] = pa[p].z; As[buf][c4+3][r] = pa[p].w;
        }
        #pragma unroll
        for (int p = 0; p < 4; p++) {
            int lin = tid + p * 128;
            int vr = lin >> 5, vd4 = (lin & 31) << 2;
            *(float4*)&Vs[buf][vr][vd4] = pv[p];
        }
    };

    ldg(0); sts(0); __syncthreads();
    for (int s = 0; s < 40; s++) {
        const int cur = s & 1;
        if (s < 39) ldg((s + 1) * 16);
        #pragma unroll
        for (int dd = 0; dd < 16; dd++) {
            float a[8], bb[8];
            *(float4*)&a[0] = *(const float4*)&As[cur][dd][tyq * 8];
            *(float4*)&a[4] = *(const float4*)&As[cur][dd][tyq * 8 + 4];
            *(float4*)&bb[0] = *(const float4*)&Vs[cur][dd][txd * 8];
            *(float4*)&bb[4] = *(const float4*)&Vs[cur][dd][txd * 8 + 4];
            #pragma unroll
            for (int i = 0; i < 8; i++)
                #pragma unroll
                for (int j = 0; j < 8; j++)
                    acc[i][j] += a[i] * bb[j];
        }
        if (s < 39) sts(cur ^ 1);
        __syncthreads();
    }

    #pragma unroll
    for (int i = 0; i < 8; i++) {
        int q = q0 + tyq * 8 + i;
        size_t base = ((size_t)(b * S_ + q)) * EMBED + h * HD + txd * 8;
        *(float4*)&g_ctx[base]     = make_float4(acc[i][0], acc[i][1], acc[i][2], acc[i][3]);
        *(float4*)&g_ctx[base + 4] = make_float4(acc[i][4], acc[i][5], acc[i][6], acc[i][7]);
    }
}

// ---------------- launcher ----------------
extern "C" void kernel_launch(void* const* d_in, const int* in_sizes, int n_in,
                              void* d_out, int out_size)
{
    const float*         Q   = (const float*)d_in[0];
    const float*         K   = (const float*)d_in[1];
    const float*         V   = (const float*)d_in[2];
    const unsigned char* pad = (const unsigned char*)d_in[4];
    const float*         Wq  = (const float*)d_in[5];
    const float*         Wk  = (const float*)d_in[6];
    const float*         Wv  = (const float*)d_in[7];
    const float*         Wo  = (const float*)d_in[8];
    const float*         rel = (const float*)d_in[9];
    float*               out = (float*)d_out;

    float *Qp, *Kp, *Vp, *ctx, *Wop;
    cudaGetSymbolAddress((void**)&Qp,  g_Qp);
    cudaGetSymbolAddress((void**)&Kp,  g_Kp);
    cudaGetSymbolAddress((void**)&Vp,  g_Vp);
    cudaGetSymbolAddress((void**)&ctx, g_ctx);
    cudaGetSymbolAddress((void**)&Wop, g_Wop);

    const int SMEM_G = 2 * 2 * 16 * 132 * 4;   // 67584
    cudaFuncSetAttribute(sgemm128<0>, cudaFuncAttributeMaxDynamicSharedMemorySize, SMEM_G);
    cudaFuncSetAttribute(sgemm128<1>, cudaFuncAttributeMaxDynamicSharedMemorySize, SMEM_G);

    dim3 gg(8, 32);
    sgemm128<0><<<gg, 256, SMEM_G>>>(Q, Wq, Qp);
    sgemm128<0><<<gg, 256, SMEM_G>>>(K, Wk, Kp);
    sgemm128<0><<<gg, 256, SMEM_G>>>(V, Wv, Vp);
    wo_permute<<<1024, 256>>>(Wo);

    qrel_gemm<<<dim3(3, 16, 32), 128>>>(rel);
    score_kernel<<<dim3(5, 16, 32), 128>>>(pad);
    softmax_band<<<4096, 256>>>();
    pv_kernel<<<dim3(16, 32), 128>>>();

    sgemm128<1><<<gg, 256, SMEM_G>>>(ctx, Wop, out);
}

// round 3
// speedup vs baseline: 2.9249x; 2.6048x over previous
#include <cuda_runtime.h>
#include <math.h>
#include <stdint.h>

#define EMBED   1024
#define NH      8
#define HD      128
#define MAXDIST 128
#define RADIUS_ 256
#define RR      257
#define B_      4
#define S_      1024
#define BHN     32
#define BAND    640

// ---------------- scratch ----------------
__device__ float g_Qp[BHN * S_ * HD];
__device__ float g_Kp[BHN * S_ * HD];
__device__ float g_Vp[BHN * S_ * HD];
__device__ float g_Qrel[BHN * S_ * RR];
__device__ float g_S[(size_t)BHN * S_ * BAND];
__device__ float g_ctx[B_ * S_ * EMBED];
__device__ float g_Wop[EMBED * EMBED];

// ---------------- tf32 helpers ----------------
__device__ __forceinline__ uint32_t f2tf(float x) {
    uint32_t r; asm("cvt.rna.tf32.f32 %0, %1;" : "=r"(r) : "f"(x)); return r;
}
__device__ __forceinline__ uint4 tf4(float4 v) {
    uint4 u; u.x = f2tf(v.x); u.y = f2tf(v.y); u.z = f2tf(v.z); u.w = f2tf(v.w); return u;
}
__device__ __forceinline__ void mma8(float* d, const uint32_t* a, const uint32_t* b) {
    asm volatile(
        "mma.sync.aligned.m16n8k8.row.col.f32.tf32.tf32.f32 "
        "{%0,%1,%2,%3}, {%4,%5,%6,%7}, {%8,%9}, {%0,%1,%2,%3};"
        : "+f"(d[0]), "+f"(d[1]), "+f"(d[2]), "+f"(d[3])
        : "r"(a[0]), "r"(a[1]), "r"(a[2]), "r"(a[3]), "r"(b[0]), "r"(b[1]));
}

// shared mainloop step: one k16 slab.  As/Bs layout: [row 0..127][k 0..15] stride 20.
// warp tile 64(m) x 32(n); m-frags 4, n-frags 4.
__device__ __forceinline__ void mma_slab(const uint32_t* As, const uint32_t* Bs,
                                         int wm, int wn, int g, int r,
                                         float acc[4][4][4])
{
    #pragma unroll
    for (int ks = 0; ks < 2; ks++) {
        uint32_t af[4][4], bf[4][2];
        #pragma unroll
        for (int i = 0; i < 4; i++) {
            const uint32_t* p = As + (wm * 64 + i * 16 + g) * 20 + ks * 8 + r;
            af[i][0] = p[0]; af[i][1] = p[160]; af[i][2] = p[4]; af[i][3] = p[164];
        }
        #pragma unroll
        for (int j = 0; j < 4; j++) {
            const uint32_t* p = Bs + (wn * 32 + j * 8 + g) * 20 + ks * 8 + r;
            bf[j][0] = p[0]; bf[j][1] = p[4];
        }
        #pragma unroll
        for (int i = 0; i < 4; i++)
            #pragma unroll
            for (int j = 0; j < 4; j++)
                mma8(acc[i][j], af[i], bf[j]);
    }
}

// ---------------- fast exp (x <= 0) ----------------
__device__ __forceinline__ float fexp(float x) {
    float z = x * 1.4426950408889634f;
    z = fmaxf(z, -127.0f);
    float n = rintf(z);
    float f = z - n;
    float p =           1.3333558e-3f;
    p = fmaf(p, f, 9.6181290e-3f);
    p = fmaf(p, f, 5.5504109e-2f);
    p = fmaf(p, f, 2.4022651e-1f);
    p = fmaf(p, f, 6.9314718e-1f);
    p = fmaf(p, f, 1.0f);
    return p * __int_as_float(((int)n + 127) << 23);
}

// ---------------- big GEMM: C = A(Mx1024) * B(Nx1024)^T ----------------
// MODE 0: scatter into [bh][s][d]; MODE 1: plain row-major
template<int MODE>
__global__ __launch_bounds__(256) void tc_gemm1024(
    const float* __restrict__ A, const float* __restrict__ Bm, float* __restrict__ C)
{
    __shared__ uint32_t As[2][2560], Bs[2][2560];
    const int tid = threadIdx.x, lane = tid & 31, wid = tid >> 5;
    const int wm = wid >> 2, wn = wid & 3, g = lane >> 2, r = lane & 3;
    const int m0 = blockIdx.y * 128, n0 = blockIdx.x * 128;
    const int lm = tid >> 2, lk4 = (tid & 3) * 4;

    float acc[4][4][4];
    #pragma unroll
    for (int i = 0; i < 4; i++) for (int j = 0; j < 4; j++) for (int e = 0; e < 4; e++) acc[i][j][e] = 0.f;

    float4 pa[2], pb[2];
    auto ldg = [&](int k0) {
        pa[0] = *(const float4*)&A[(size_t)(m0 + lm) * 1024 + k0 + lk4];
        pa[1] = *(const float4*)&A[(size_t)(m0 + lm + 64) * 1024 + k0 + lk4];
        pb[0] = *(const float4*)&Bm[(size_t)(n0 + lm) * 1024 + k0 + lk4];
        pb[1] = *(const float4*)&Bm[(size_t)(n0 + lm + 64) * 1024 + k0 + lk4];
    };
    auto sts = [&](int buf) {
        *(uint4*)&As[buf][lm * 20 + lk4]        = tf4(pa[0]);
        *(uint4*)&As[buf][(lm + 64) * 20 + lk4] = tf4(pa[1]);
        *(uint4*)&Bs[buf][lm * 20 + lk4]        = tf4(pb[0]);
        *(uint4*)&Bs[buf][(lm + 64) * 20 + lk4] = tf4(pb[1]);
    };

    ldg(0); sts(0); __syncthreads();
    for (int s = 0; s < 64; s++) {
        int cur = s & 1;
        if (s < 63) ldg((s + 1) * 16);
        mma_slab(As[cur], Bs[cur], wm, wn, g, r, acc);
        if (s < 63) sts(cur ^ 1);
        __syncthreads();
    }

    #pragma unroll
    for (int i = 0; i < 4; i++) {
        int row0 = m0 + wm * 64 + i * 16 + g;
        #pragma unroll
        for (int j = 0; j < 4; j++) {
            int col = n0 + wn * 32 + j * 8 + r * 2;
            if (MODE == 0) {
                int h = col >> 7, d = col & 127;
                #pragma unroll
                for (int half = 0; half < 2; half++) {
                    int m = row0 + half * 8;
                    int b = m >> 10, ss = m & 1023;
                    size_t base = (((size_t)(b * NH + h)) * S_ + ss) * HD + d;
                    *(float2*)&C[base] = make_float2(acc[i][j][half * 2], acc[i][j][half * 2 + 1]);
                }
            } else {
                *(float2*)&C[(size_t)row0 * 1024 + col]       = make_float2(acc[i][j][0], acc[i][j][1]);
                *(float2*)&C[(size_t)(row0 + 8) * 1024 + col] = make_float2(acc[i][j][2], acc[i][j][3]);
            }
        }
    }
}

// ---------------- Wo permute ----------------
__global__ void wo_permute(const float* __restrict__ Wo)
{
    int n = blockIdx.x;
    for (int f = threadIdx.x; f < 1024; f += 256) {
        int h = f >> 7, d = f & 127;
        g_Wop[n * 1024 + f] = Wo[n * 1024 + d * 8 + h];
    }
}

// ---------------- Qrel: [bh][q][r] = Qp[q].rel[h][r]  (M=1024,N=257,K=128) ----------------
__global__ __launch_bounds__(256) void tc_qrel(const float* __restrict__ rel)
{
    __shared__ uint32_t As[2][2560], Bs[2][2560];
    const int tid = threadIdx.x, lane = tid & 31, wid = tid >> 5;
    const int wm = wid >> 2, wn = wid & 3, g = lane >> 2, r = lane & 3;
    const int r0 = blockIdx.x * 128, q0 = blockIdx.y * 128, bh = blockIdx.z;
    const int h = bh & 7;
    const float* Aq = g_Qp + (size_t)bh * S_ * HD;
    const float* Br = rel + (size_t)h * RR * HD;
    const int lm = tid >> 2, lk4 = (tid & 3) * 4;

    float acc[4][4][4];
    #pragma unroll
    for (int i = 0; i < 4; i++) for (int j = 0; j < 4; j++) for (int e = 0; e < 4; e++) acc[i][j][e] = 0.f;

    float4 pa[2], pb[2];
    auto ldg = [&](int k0) {
        pa[0] = *(const float4*)&Aq[(size_t)(q0 + lm) * HD + k0 + lk4];
        pa[1] = *(const float4*)&Aq[(size_t)(q0 + lm + 64) * HD + k0 + lk4];
        #pragma unroll
        for (int p = 0; p < 2; p++) {
            int rg = r0 + lm + p * 64;
            pb[p] = (rg < RR) ? *(const float4*)&Br[(size_t)rg * HD + k0 + lk4]
                              : make_float4(0.f, 0.f, 0.f, 0.f);
        }
    };
    auto sts = [&](int buf) {
        *(uint4*)&As[buf][lm * 20 + lk4]        = tf4(pa[0]);
        *(uint4*)&As[buf][(lm + 64) * 20 + lk4] = tf4(pa[1]);
        *(uint4*)&Bs[buf][lm * 20 + lk4]        = tf4(pb[0]);
        *(uint4*)&Bs[buf][(lm + 64) * 20 + lk4] = tf4(pb[1]);
    };

    ldg(0); sts(0); __syncthreads();
    for (int s = 0; s < 8; s++) {
        int cur = s & 1;
        if (s < 7) ldg((s + 1) * 16);
        mma_slab(As[cur], Bs[cur], wm, wn, g, r, acc);
        if (s < 7) sts(cur ^ 1);
        __syncthreads();
    }

    #pragma unroll
    for (int i = 0; i < 4; i++) {
        int row0 = q0 + wm * 64 + i * 16 + g;
        #pragma unroll
        for (int j = 0; j < 4; j++) {
            int col = r0 + wn * 32 + j * 8 + r * 2;
            #pragma unroll
            for (int half = 0; half < 2; half++) {
                size_t base = ((size_t)bh * S_ + row0 + half * 8) * RR;
                if (col < RR)     g_Qrel[base + col]     = acc[i][j][half * 2];
                if (col + 1 < RR) g_Qrel[base + col + 1] = acc[i][j][half * 2 + 1];
            }
        }
    }
}

// ---------------- banded scores (M=1024 q, N=640 band, K=128) ----------------
__global__ __launch_bounds__(256) void tc_score(const unsigned char* __restrict__ pad)
{
    __shared__ uint32_t As[2][2560], Bs[2][2560];
    const int tid = threadIdx.x, lane = tid & 31, wid = tid >> 5;
    const int wm = wid >> 2, wn = wid & 3, g = lane >> 2, r = lane & 3;
    const int kt0 = blockIdx.x * 128, q0 = blockIdx.y * 128, bh = blockIdx.z;
    const int b = bh >> 3;
    const int kbase = q0 - RADIUS_;
    const float* Aq = g_Qp + (size_t)bh * S_ * HD;
    const float* Kb = g_Kp + (size_t)bh * S_ * HD;
    const int lm = tid >> 2, lk4 = (tid & 3) * 4;

    float acc[4][4][4];
    #pragma unroll
    for (int i = 0; i < 4; i++) for (int j = 0; j < 4; j++) for (int e = 0; e < 4; e++) acc[i][j][e] = 0.f;

    float4 pa[2], pb[2];
    auto ldg = [&](int k0) {
        pa[0] = *(const float4*)&Aq[(size_t)(q0 + lm) * HD + k0 + lk4];
        pa[1] = *(const float4*)&Aq[(size_t)(q0 + lm + 64) * HD + k0 + lk4];
        #pragma unroll
        for (int p = 0; p < 2; p++) {
            int k = kbase + kt0 + lm + p * 64;
            pb[p] = (k >= 0 && k < S_) ? *(const float4*)&Kb[(size_t)k * HD + k0 + lk4]
                                       : make_float4(0.f, 0.f, 0.f, 0.f);
        }
    };
    auto sts = [&](int buf) {
        *(uint4*)&As[buf][lm * 20 + lk4]        = tf4(pa[0]);
        *(uint4*)&As[buf][(lm + 64) * 20 + lk4] = tf4(pa[1]);
        *(uint4*)&Bs[buf][lm * 20 + lk4]        = tf4(pb[0]);
        *(uint4*)&Bs[buf][(lm + 64) * 20 + lk4] = tf4(pb[1]);
    };

    ldg(0); sts(0); __syncthreads();
    for (int s = 0; s < 8; s++) {
        int cur = s & 1;
        if (s < 7) ldg((s + 1) * 16);
        mma_slab(As[cur], Bs[cur], wm, wn, g, r, acc);
        if (s < 7) sts(cur ^ 1);
        __syncthreads();
    }

    const float scale = 0.08838834764831845f;
    #pragma unroll
    for (int i = 0; i < 4; i++) {
        #pragma unroll
        for (int half = 0; half < 2; half++) {
            int qg = q0 + wm * 64 + i * 16 + g + half * 8;
            size_t qrow = (size_t)bh * S_ + qg;
            #pragma unroll
            for (int j = 0; j < 4; j++) {
                int kk0 = kt0 + wn * 32 + j * 8 + r * 2;
                float v[2];
                #pragma unroll
                for (int e = 0; e < 2; e++) {
                    int kk = kk0 + e;
                    int k = kbase + kk;
                    int dlt = k - qg;
                    float val = -INFINITY;
                    if (k >= 0 && k < S_ && dlt >= -RADIUS_ && dlt <= RADIUS_ &&
                        pad[b * S_ + k] == 0) {
                        int rid = dlt < -MAXDIST ? -MAXDIST : (dlt > MAXDIST ? MAXDIST : dlt);
                        rid += MAXDIST;
                        val = (acc[i][j][half * 2 + e] + g_Qrel[qrow * RR + rid]) * scale;
                    }
                    v[e] = val;
                }
                *(float2*)&g_S[qrow * BAND + kk0] = make_float2(v[0], v[1]);
            }
        }
    }
}

// ---------------- band softmax ----------------
__global__ __launch_bounds__(256) void softmax_band()
{
    int row  = blockIdx.x * 8 + (threadIdx.x >> 5);
    int lane = threadIdx.x & 31;
    float* Srow = g_S + (size_t)row * BAND;

    float4 v[5];
    #pragma unroll
    for (int p = 0; p < 5; p++) v[p] = *(const float4*)&Srow[p * 128 + lane * 4];

    float m = -INFINITY;
    #pragma unroll
    for (int p = 0; p < 5; p++)
        m = fmaxf(m, fmaxf(fmaxf(v[p].x, v[p].y), fmaxf(v[p].z, v[p].w)));
    #pragma unroll
    for (int o = 16; o > 0; o >>= 1) m = fmaxf(m, __shfl_xor_sync(0xffffffffu, m, o));

    float sum = 0.f;
    #pragma unroll
    for (int p = 0; p < 5; p++) {
        v[p].x = fexp(v[p].x - m); v[p].y = fexp(v[p].y - m);
        v[p].z = fexp(v[p].z - m); v[p].w = fexp(v[p].w - m);
        sum += v[p].x + v[p].y + v[p].z + v[p].w;
    }
    #pragma unroll
    for (int o = 16; o > 0; o >>= 1) sum += __shfl_xor_sync(0xffffffffu, sum, o);

    float inv = 1.f / sum;
    #pragma unroll
    for (int p = 0; p < 5; p++) {
        v[p].x *= inv; v[p].y *= inv; v[p].z *= inv; v[p].w *= inv;
        *(float4*)&Srow[p * 128 + lane * 4] = v[p];
    }
}

// ---------------- PV: ctx[b][s][h*128+d] (M=1024 q, N=128 d, K=640) ----------------
__global__ __launch_bounds__(256) void tc_pv()
{
    __shared__ uint32_t As[2][2560], Bs[2][2560];
    const int tid = threadIdx.x, lane = tid & 31, wid = tid >> 5;
    const int wm = wid >> 2, wn = wid & 3, g = lane >> 2, r = lane & 3;
    const int q0 = blockIdx.x * 128, bh = blockIdx.y;
    const int b = bh >> 3, h = bh & 7;
    const int kbase = q0 - RADIUS_;
    const float* Vb = g_Vp + (size_t)bh * S_ * HD;
    const int lm = tid >> 2, lk4 = (tid & 3) * 4;
    // V transposed-load mapping
    const int vkk = lane & 15;
    const int vd  = wid * 16 + (lane >> 4) * 4;

    float acc[4][4][4];
    #pragma unroll
    for (int i = 0; i < 4; i++) for (int j = 0; j < 4; j++) for (int e = 0; e < 4; e++) acc[i][j][e] = 0.f;

    float4 pa[2], pb[2];
    auto ldg = [&](int k0) {
        pa[0] = *(const float4*)&g_S[((size_t)bh * S_ + q0 + lm) * BAND + k0 + lk4];
        pa[1] = *(const float4*)&g_S[((size_t)bh * S_ + q0 + lm + 64) * BAND + k0 + lk4];
        int k = kbase + k0 + vkk;
        bool ok = (k >= 0 && k < S_);
        pb[0] = ok ? *(const float4*)&Vb[(size_t)k * HD + vd]     : make_float4(0.f, 0.f, 0.f, 0.f);
        pb[1] = ok ? *(const float4*)&Vb[(size_t)k * HD + vd + 8] : make_float4(0.f, 0.f, 0.f, 0.f);
    };
    auto sts = [&](int buf) {
        *(uint4*)&As[buf][lm * 20 + lk4]        = tf4(pa[0]);
        *(uint4*)&As[buf][(lm + 64) * 20 + lk4] = tf4(pa[1]);
        #pragma unroll
        for (int p = 0; p < 2; p++) {
            int d0 = vd + p * 8;
            float vv[4] = { p ? pb[1].x : pb[0].x, p ? pb[1].y : pb[0].y,
                            p ? pb[1].z : pb[0].z, p ? pb[1].w : pb[0].w };
            #pragma unroll
            for (int i = 0; i < 4; i++)
                Bs[buf][(d0 + i) * 20 + vkk] = f2tf(vv[i]);
        }
    };

    ldg(0); sts(0); __syncthreads();
    for (int s = 0; s < 40; s++) {
        int cur = s & 1;
        if (s < 39) ldg((s + 1) * 16);
        mma_slab(As[cur], Bs[cur], wm, wn, g, r, acc);
        if (s < 39) sts(cur ^ 1);
        __syncthreads();
    }

    #pragma unroll
    for (int i = 0; i < 4; i++) {
        #pragma unroll
        for (int half = 0; half < 2; half++) {
            int q = q0 + wm * 64 + i * 16 + g + half * 8;
            size_t base = ((size_t)(b * S_ + q)) * EMBED + h * HD;
            #pragma unroll
            for (int j = 0; j < 4; j++) {
                int d = wn * 32 + j * 8 + r * 2;
                *(float2*)&g_ctx[base + d] =
                    make_float2(acc[i][j][half * 2], acc[i][j][half * 2 + 1]);
            }
        }
    }
}

// ---------------- launcher ----------------
extern "C" void kernel_launch(void* const* d_in, const int* in_sizes, int n_in,
                              void* d_out, int out_size)
{
    const float*         Q   = (const float*)d_in[0];
    const float*         K   = (const float*)d_in[1];
    const float*         V   = (const float*)d_in[2];
    const unsigned char* pad = (const unsigned char*)d_in[4];
    const float*         Wq  = (const float*)d_in[5];
    const float*         Wk  = (const float*)d_in[6];
    const float*         Wv  = (const float*)d_in[7];
    const float*         Wo  = (const float*)d_in[8];
    const float*         rel = (const float*)d_in[9];
    float*               out = (float*)d_out;

    float *Qp, *Kp, *Vp, *ctx, *Wop;
    cudaGetSymbolAddress((void**)&Qp,  g_Qp);
    cudaGetSymbolAddress((void**)&Kp,  g_Kp);
    cudaGetSymbolAddress((void**)&Vp,  g_Vp);
    cudaGetSymbolAddress((void**)&ctx, g_ctx);
    cudaGetSymbolAddress((void**)&Wop, g_Wop);

    dim3 gg(8, 32);
    tc_gemm1024<0><<<gg, 256>>>(Q, Wq, Qp);
    tc_gemm1024<0><<<gg, 256>>>(K, Wk, Kp);
    tc_gemm1024<0><<<gg, 256>>>(V, Wv, Vp);
    wo_permute<<<1024, 256>>>(Wo);

    tc_qrel<<<dim3(3, 8, 32), 256>>>(rel);
    tc_score<<<dim3(5, 8, 32), 256>>>(pad);
    softmax_band<<<4096, 256>>>();
    tc_pv<<<dim3(8, 32), 256>>>();

    tc_gemm1024<1><<<gg, 256>>>(ctx, Wop, out);
}

// round 5
// speedup vs baseline: 2.9276x; 1.0009x over previous
#include <cuda_runtime.h>
#include <math.h>
#include <stdint.h>

#define EMBED   1024
#define NH      8
#define HD      128
#define MAXDIST 128
#define RADIUS_ 256
#define RR      257
#define B_      4
#define S_      1024
#define BHN     32
#define BAND    640

// ---------------- scratch ----------------
__device__ float g_Qp[BHN * S_ * HD];
__device__ float g_Kp[BHN * S_ * HD];
__device__ float g_Vp[BHN * S_ * HD];
__device__ float g_Qrel[BHN * S_ * RR];
__device__ float g_S[(size_t)BHN * S_ * BAND];   // raw masked energies
__device__ float g_ctx[B_ * S_ * EMBED];
__device__ float g_Wop[EMBED * EMBED];

// ---------------- tf32 helpers ----------------
__device__ __forceinline__ uint32_t f2tf(float x) {
    uint32_t r; asm("cvt.rna.tf32.f32 %0, %1;" : "=r"(r) : "f"(x)); return r;
}
__device__ __forceinline__ uint4 tf4(float4 v) {
    uint4 u; u.x = f2tf(v.x); u.y = f2tf(v.y); u.z = f2tf(v.z); u.w = f2tf(v.w); return u;
}
__device__ __forceinline__ void mma8(float* d, const uint32_t* a, const uint32_t* b) {
    asm volatile(
        "mma.sync.aligned.m16n8k8.row.col.f32.tf32.tf32.f32 "
        "{%0,%1,%2,%3}, {%4,%5,%6,%7}, {%8,%9}, {%0,%1,%2,%3};"
        : "+f"(d[0]), "+f"(d[1]), "+f"(d[2]), "+f"(d[3])
        : "r"(a[0]), "r"(a[1]), "r"(a[2]), "r"(a[3]), "r"(b[0]), "r"(b[1]));
}

// ---------------- fast exp (x <= 0, handles -inf) ----------------
__device__ __forceinline__ float fexp(float x) {
    float z = x * 1.4426950408889634f;
    z = fmaxf(z, -127.0f);
    float n = rintf(z);
    float f = z - n;
    float p =           1.3333558e-3f;
    p = fmaf(p, f, 9.6181290e-3f);
    p = fmaf(p, f, 5.5504109e-2f);
    p = fmaf(p, f, 2.4022651e-1f);
    p = fmaf(p, f, 6.9314718e-1f);
    p = fmaf(p, f, 1.0f);
    return p * __int_as_float(((int)n + 127) << 23);
}

// ---------------- wide GEMM body: C = A(Mx1024) * B(Nx1024)^T ----------------
// CTA tile 128m x 256n, warp tile 64x64 (8 warps: wm 0..1 x wn 0..3), k16 slabs.
// dynamic smem: As 2x2560 words, Bs 2x5120 words  (61440 bytes)
template<int MODE>
__device__ __forceinline__ void gemm_w_body(
    const float* __restrict__ A, const float* __restrict__ Bm, float* __restrict__ C,
    uint32_t* sm, int m0, int n0)
{
    uint32_t* AsB = sm;            // [2][2560]
    uint32_t* BsB = sm + 5120;     // [2][5120]

    const int tid = threadIdx.x, lane = tid & 31, wid = tid >> 5;
    const int wm = wid >> 2, wn = wid & 3, g = lane >> 2, r = lane & 3;
    const int lm = tid >> 2, lk4 = (tid & 3) * 4;

    float acc[4][8][4];
    #pragma unroll
    for (int i = 0; i < 4; i++) for (int j = 0; j < 8; j++) for (int e = 0; e < 4; e++)
        acc[i][j][e] = 0.f;

    float4 pa[2], pb[4];
    auto ldg = [&](int k0) {
        pa[0] = *(const float4*)&A[(size_t)(m0 + lm) * 1024 + k0 + lk4];
        pa[1] = *(const float4*)&A[(size_t)(m0 + lm + 64) * 1024 + k0 + lk4];
        #pragma unroll
        for (int p = 0; p < 4; p++)
            pb[p] = *(const float4*)&Bm[(size_t)(n0 + lm + p * 64) * 1024 + k0 + lk4];
    };
    auto sts = [&](int buf) {
        uint32_t* As = AsB + buf * 2560;
        uint32_t* Bs = BsB + buf * 5120;
        *(uint4*)&As[lm * 20 + lk4]        = tf4(pa[0]);
        *(uint4*)&As[(lm + 64) * 20 + lk4] = tf4(pa[1]);
        #pragma unroll
        for (int p = 0; p < 4; p++)
            *(uint4*)&Bs[(lm + p * 64) * 20 + lk4] = tf4(pb[p]);
    };

    ldg(0); sts(0); __syncthreads();
    for (int s = 0; s < 64; s++) {
        int cur = s & 1;
        if (s < 63) ldg((s + 1) * 16);
        const uint32_t* As = AsB + cur * 2560;
        const uint32_t* Bs = BsB + cur * 5120;
        #pragma unroll
        for (int ks = 0; ks < 2; ks++) {
            uint32_t af[4][4], bf[8][2];
            #pragma unroll
            for (int i = 0; i < 4; i++) {
                const uint32_t* p = As + (wm * 64 + i * 16 + g) * 20 + ks * 8 + r;
                af[i][0] = p[0]; af[i][1] = p[160]; af[i][2] = p[4]; af[i][3] = p[164];
            }
            #pragma unroll
            for (int j = 0; j < 8; j++) {
                const uint32_t* p = Bs + (wn * 64 + j * 8 + g) * 20 + ks * 8 + r;
                bf[j][0] = p[0]; bf[j][1] = p[4];
            }
            #pragma unroll
            for (int i = 0; i < 4; i++)
                #pragma unroll
                for (int j = 0; j < 8; j++)
                    mma8(acc[i][j], af[i], bf[j]);
        }
        if (s < 63) sts(cur ^ 1);
        __syncthreads();
    }

    #pragma unroll
    for (int i = 0; i < 4; i++) {
        int row0 = m0 + wm * 64 + i * 16 + g;
        #pragma unroll
        for (int j = 0; j < 8; j++) {
            int col = n0 + wn * 64 + j * 8 + r * 2;
            if (MODE == 0) {
                int h = col >> 7, d = col & 127;
                #pragma unroll
                for (int half = 0; half < 2; half++) {
                    int m = row0 + half * 8;
                    int b = m >> 10, ss = m & 1023;
                    *(float2*)&C[(((size_t)(b * NH + h)) * S_ + ss) * HD + d] =
                        make_float2(acc[i][j][half * 2], acc[i][j][half * 2 + 1]);
                }
            } else {
                *(float2*)&C[(size_t)row0 * 1024 + col]       = make_float2(acc[i][j][0], acc[i][j][1]);
                *(float2*)&C[(size_t)(row0 + 8) * 1024 + col] = make_float2(acc[i][j][2], acc[i][j][3]);
            }
        }
    }
}

// 3 projections in one launch (z selects input/weight/output)
__global__ __launch_bounds__(256) void proj3_gemm(
    const float* __restrict__ Q, const float* __restrict__ K, const float* __restrict__ V,
    const float* __restrict__ Wq, const float* __restrict__ Wk, const float* __restrict__ Wv,
    float* __restrict__ Qp, float* __restrict__ Kp, float* __restrict__ Vp)
{
    extern __shared__ uint32_t sm[];
    int z = blockIdx.z;
    const float* A  = (z == 0) ? Q  : (z == 1) ? K  : V;
    const float* Bm = (z == 0) ? Wq : (z == 1) ? Wk : Wv;
    float*       C  = (z == 0) ? Qp : (z == 1) ? Kp : Vp;
    gemm_w_body<0>(A, Bm, C, sm, blockIdx.y * 128, blockIdx.x * 256);
}

__global__ __launch_bounds__(256) void out_gemm(
    const float* __restrict__ A, const float* __restrict__ Bm, float* __restrict__ C)
{
    extern __shared__ uint32_t sm[];
    gemm_w_body<1>(A, Bm, C, sm, blockIdx.y * 128, blockIdx.x * 256);
}

// ---------------- Wo permute ----------------
__global__ void wo_permute(const float* __restrict__ Wo)
{
    int n = blockIdx.x;
    for (int f = threadIdx.x; f < 1024; f += 256) {
        int h = f >> 7, d = f & 127;
        g_Wop[n * 1024 + f] = Wo[n * 1024 + d * 8 + h];
    }
}

// ---------------- legacy slab for attention kernels (128x128 tile) ----------------
__device__ __forceinline__ void mma_slab(const uint32_t* As, const uint32_t* Bs,
                                         int wm, int wn, int g, int r,
                                         float acc[4][4][4])
{
    #pragma unroll
    for (int ks = 0; ks < 2; ks++) {
        uint32_t af[4][4], bf[4][2];
        #pragma unroll
        for (int i = 0; i < 4; i++) {
            const uint32_t* p = As + (wm * 64 + i * 16 + g) * 20 + ks * 8 + r;
            af[i][0] = p[0]; af[i][1] = p[160]; af[i][2] = p[4]; af[i][3] = p[164];
        }
        #pragma unroll
        for (int j = 0; j < 4; j++) {
            const uint32_t* p = Bs + (wn * 32 + j * 8 + g) * 20 + ks * 8 + r;
            bf[j][0] = p[0]; bf[j][1] = p[4];
        }
        #pragma unroll
        for (int i = 0; i < 4; i++)
            #pragma unroll
            for (int j = 0; j < 4; j++)
                mma8(acc[i][j], af[i], bf[j]);
    }
}

// ---------------- Qrel ----------------
__global__ __launch_bounds__(256) void tc_qrel(const float* __restrict__ rel)
{
    __shared__ uint32_t As[2][2560], Bs[2][2560];
    const int tid = threadIdx.x, lane = tid & 31, wid = tid >> 5;
    const int wm = wid >> 2, wn = wid & 3, g = lane >> 2, r = lane & 3;
    const int r0 = blockIdx.x * 128, q0 = blockIdx.y * 128, bh = blockIdx.z;
    const int h = bh & 7;
    const float* Aq = g_Qp + (size_t)bh * S_ * HD;
    const float* Br = rel + (size_t)h * RR * HD;
    const int lm = tid >> 2, lk4 = (tid & 3) * 4;

    float acc[4][4][4];
    #pragma unroll
    for (int i = 0; i < 4; i++) for (int j = 0; j < 4; j++) for (int e = 0; e < 4; e++) acc[i][j][e] = 0.f;

    float4 pa[2], pb[2];
    auto ldg = [&](int k0) {
        pa[0] = *(const float4*)&Aq[(size_t)(q0 + lm) * HD + k0 + lk4];
        pa[1] = *(const float4*)&Aq[(size_t)(q0 + lm + 64) * HD + k0 + lk4];
        #pragma unroll
        for (int p = 0; p < 2; p++) {
            int rg = r0 + lm + p * 64;
            pb[p] = (rg < RR) ? *(const float4*)&Br[(size_t)rg * HD + k0 + lk4]
                              : make_float4(0.f, 0.f, 0.f, 0.f);
        }
    };
    auto sts = [&](int buf) {
        *(uint4*)&As[buf][lm * 20 + lk4]        = tf4(pa[0]);
        *(uint4*)&As[buf][(lm + 64) * 20 + lk4] = tf4(pa[1]);
        *(uint4*)&Bs[buf][lm * 20 + lk4]        = tf4(pb[0]);
        *(uint4*)&Bs[buf][(lm + 64) * 20 + lk4] = tf4(pb[1]);
    };

    ldg(0); sts(0); __syncthreads();
    for (int s = 0; s < 8; s++) {
        int cur = s & 1;
        if (s < 7) ldg((s + 1) * 16);
        mma_slab(As[cur], Bs[cur], wm, wn, g, r, acc);
        if (s < 7) sts(cur ^ 1);
        __syncthreads();
    }

    #pragma unroll
    for (int i = 0; i < 4; i++) {
        int row0 = q0 + wm * 64 + i * 16 + g;
        #pragma unroll
        for (int j = 0; j < 4; j++) {
            int col = r0 + wn * 32 + j * 8 + r * 2;
            #pragma unroll
            for (int half = 0; half < 2; half++) {
                size_t base = ((size_t)bh * S_ + row0 + half * 8) * RR;
                if (col < RR)     g_Qrel[base + col]     = acc[i][j][half * 2];
                if (col + 1 < RR) g_Qrel[base + col + 1] = acc[i][j][half * 2 + 1];
            }
        }
    }
}

// ---------------- banded scores (raw masked energies) ----------------
__global__ __launch_bounds__(256) void tc_score(const unsigned char* __restrict__ pad)
{
    __shared__ uint32_t As[2][2560], Bs[2][2560];
    const int tid = threadIdx.x, lane = tid & 31, wid = tid >> 5;
    const int wm = wid >> 2, wn = wid & 3, g = lane >> 2, r = lane & 3;
    const int kt0 = blockIdx.x * 128, q0 = blockIdx.y * 128, bh = blockIdx.z;
    const int b = bh >> 3;
    const int kbase = q0 - RADIUS_;
    const float* Aq = g_Qp + (size_t)bh * S_ * HD;
    const float* Kb = g_Kp + (size_t)bh * S_ * HD;
    const int lm = tid >> 2, lk4 = (tid & 3) * 4;

    float acc[4][4][4];
    #pragma unroll
    for (int i = 0; i < 4; i++) for (int j = 0; j < 4; j++) for (int e = 0; e < 4; e++) acc[i][j][e] = 0.f;

    float4 pa[2], pb[2];
    auto ldg = [&](int k0) {
        pa[0] = *(const float4*)&Aq[(size_t)(q0 + lm) * HD + k0 + lk4];
        pa[1] = *(const float4*)&Aq[(size_t)(q0 + lm + 64) * HD + k0 + lk4];
        #pragma unroll
        for (int p = 0; p < 2; p++) {
            int k = kbase + kt0 + lm + p * 64;
            pb[p] = (k >= 0 && k < S_) ? *(const float4*)&Kb[(size_t)k * HD + k0 + lk4]
                                       : make_float4(0.f, 0.f, 0.f, 0.f);
        }
    };
    auto sts = [&](int buf) {
        *(uint4*)&As[buf][lm * 20 + lk4]        = tf4(pa[0]);
        *(uint4*)&As[buf][(lm + 64) * 20 + lk4] = tf4(pa[1]);
        *(uint4*)&Bs[buf][lm * 20 + lk4]        = tf4(pb[0]);
        *(uint4*)&Bs[buf][(lm + 64) * 20 + lk4] = tf4(pb[1]);
    };

    ldg(0); sts(0); __syncthreads();
    for (int s = 0; s < 8; s++) {
        int cur = s & 1;
        if (s < 7) ldg((s + 1) * 16);
        mma_slab(As[cur], Bs[cur], wm, wn, g, r, acc);
        if (s < 7) sts(cur ^ 1);
        __syncthreads();
    }

    const float scale = 0.08838834764831845f;
    #pragma unroll
    for (int i = 0; i < 4; i++) {
        #pragma unroll
        for (int half = 0; half < 2; half++) {
            int qg = q0 + wm * 64 + i * 16 + g + half * 8;
            size_t qrow = (size_t)bh * S_ + qg;
            #pragma unroll
            for (int j = 0; j < 4; j++) {
                int kk0 = kt0 + wn * 32 + j * 8 + r * 2;
                float v[2];
                #pragma unroll
                for (int e = 0; e < 2; e++) {
                    int kk = kk0 + e;
                    int k = kbase + kk;
                    int dlt = k - qg;
                    float val = -INFINITY;
                    if (k >= 0 && k < S_ && dlt >= -RADIUS_ && dlt <= RADIUS_ &&
                        pad[b * S_ + k] == 0) {
                        int rid = dlt < -MAXDIST ? -MAXDIST : (dlt > MAXDIST ? MAXDIST : dlt);
                        rid += MAXDIST;
                        val = (acc[i][j][half * 2 + e] + g_Qrel[qrow * RR + rid]) * scale;
                    }
                    v[e] = val;
                }
                *(float2*)&g_S[qrow * BAND + kk0] = make_float2(v[0], v[1]);
            }
        }
    }
}

// ---------------- PV with fused softmax ----------------
__global__ __launch_bounds__(256) void tc_pv()
{
    __shared__ uint32_t As[2][2560], Bs[2][2560];
    __shared__ float sM[128], sI[128];
    const int tid = threadIdx.x, lane = tid & 31, wid = tid >> 5;
    const int wm = wid >> 2, wn = wid & 3, g = lane >> 2, r = lane & 3;
    const int q0 = blockIdx.x * 128, bh = blockIdx.y;
    const int b = bh >> 3, h = bh & 7;
    const int kbase = q0 - RADIUS_;
    const float* Vb = g_Vp + (size_t)bh * S_ * HD;
    const float* Sbase = g_S + ((size_t)bh * S_ + q0) * BAND;
    const int lm = tid >> 2, lk4 = (tid & 3) * 4;
    const int vkk = lane & 15;
    const int vd  = wid * 16 + (lane >> 4) * 4;

    // ---- phase 1: per-row max & inverse sum over the raw band ----
    for (int rr = 0; rr < 16; rr++) {
        int row = wid * 16 + rr;
        const float* Srow = Sbase + (size_t)row * BAND;
        float4 v[5];
        #pragma unroll
        for (int p = 0; p < 5; p++) v[p] = *(const float4*)&Srow[p * 128 + lane * 4];
        float m = -INFINITY;
        #pragma unroll
        for (int p = 0; p < 5; p++)
            m = fmaxf(m, fmaxf(fmaxf(v[p].x, v[p].y), fmaxf(v[p].z, v[p].w)));
        #pragma unroll
        for (int o = 16; o > 0; o >>= 1) m = fmaxf(m, __shfl_xor_sync(0xffffffffu, m, o));
        float sum = 0.f;
        #pragma unroll
        for (int p = 0; p < 5; p++)
            sum += fexp(v[p].x - m) + fexp(v[p].y - m) + fexp(v[p].z - m) + fexp(v[p].w - m);
        #pragma unroll
        for (int o = 16; o > 0; o >>= 1) sum += __shfl_xor_sync(0xffffffffu, sum, o);
        if (lane == 0) { sM[row] = m; sI[row] = 1.f / sum; }
    }
    __syncthreads();

    const float m0v = sM[lm],      i0v = sI[lm];
    const float m1v = sM[lm + 64], i1v = sI[lm + 64];

    float acc[4][4][4];
    #pragma unroll
    for (int i = 0; i < 4; i++) for (int j = 0; j < 4; j++) for (int e = 0; e < 4; e++) acc[i][j][e] = 0.f;

    float4 pa[2], pb[2];
    auto ldg = [&](int k0) {
        pa[0] = *(const float4*)&Sbase[(size_t)lm * BAND + k0 + lk4];
        pa[1] = *(const float4*)&Sbase[(size_t)(lm + 64) * BAND + k0 + lk4];
        int k = kbase + k0 + vkk;
        bool ok = (k >= 0 && k < S_);
        pb[0] = ok ? *(const float4*)&Vb[(size_t)k * HD + vd]     : make_float4(0.f, 0.f, 0.f, 0.f);
        pb[1] = ok ? *(const float4*)&Vb[(size_t)k * HD + vd + 8] : make_float4(0.f, 0.f, 0.f, 0.f);
    };
    auto sts = [&](int buf) {
        uint4 u0, u1;
        u0.x = f2tf(fexp(pa[0].x - m0v) * i0v); u0.y = f2tf(fexp(pa[0].y - m0v) * i0v);
        u0.z = f2tf(fexp(pa[0].z - m0v) * i0v); u0.w = f2tf(fexp(pa[0].w - m0v) * i0v);
        u1.x = f2tf(fexp(pa[1].x - m1v) * i1v); u1.y = f2tf(fexp(pa[1].y - m1v) * i1v);
        u1.z = f2tf(fexp(pa[1].z - m1v) * i1v); u1.w = f2tf(fexp(pa[1].w - m1v) * i1v);
        *(uint4*)&As[buf][lm * 20 + lk4]        = u0;
        *(uint4*)&As[buf][(lm + 64) * 20 + lk4] = u1;
        #pragma unroll
        for (int p = 0; p < 2; p++) {
            int d0 = vd + p * 8;
            float vv[4] = { p ? pb[1].x : pb[0].x, p ? pb[1].y : pb[0].y,
                            p ? pb[1].z : pb[0].z, p ? pb[1].w : pb[0].w };
            #pragma unroll
            for (int i = 0; i < 4; i++)
                Bs[buf][(d0 + i) * 20 + vkk] = f2tf(vv[i]);
        }
    };

    ldg(0); sts(0); __syncthreads();
    for (int s = 0; s < 40; s++) {
        int cur = s & 1;
        if (s < 39) ldg((s + 1) * 16);
        mma_slab(As[cur], Bs[cur], wm, wn, g, r, acc);
        if (s < 39) sts(cur ^ 1);
        __syncthreads();
    }

    #pragma unroll
    for (int i = 0; i < 4; i++) {
        #pragma unroll
        for (int half = 0; half < 2; half++) {
            int q = q0 + wm * 64 + i * 16 + g + half * 8;
            size_t base = ((size_t)(b * S_ + q)) * EMBED + h * HD;
            #pragma unroll
            for (int j = 0; j < 4; j++) {
                int d = wn * 32 + j * 8 + r * 2;
                *(float2*)&g_ctx[base + d] =
                    make_float2(acc[i][j][half * 2], acc[i][j][half * 2 + 1]);
            }
        }
    }
}

// ---------------- launcher ----------------
extern "C" void kernel_launch(void* const* d_in, const int* in_sizes, int n_in,
                              void* d_out, int out_size)
{
    const float*         Q   = (const float*)d_in[0];
    const float*         K   = (const float*)d_in[1];
    const float*         V   = (const float*)d_in[2];
    const unsigned char* pad = (const unsigned char*)d_in[4];
    const float*         Wq  = (const float*)d_in[5];
    const float*         Wk  = (const float*)d_in[6];
    const float*         Wv  = (const float*)d_in[7];
    const float*         Wo  = (const float*)d_in[8];
    const float*         rel = (const float*)d_in[9];
    float*               out = (float*)d_out;

    float *Qp, *Kp, *Vp, *ctx, *Wop;
    cudaGetSymbolAddress((void**)&Qp,  g_Qp);
    cudaGetSymbolAddress((void**)&Kp,  g_Kp);
    cudaGetSymbolAddress((void**)&Vp,  g_Vp);
    cudaGetSymbolAddress((void**)&ctx, g_ctx);
    cudaGetSymbolAddress((void**)&Wop, g_Wop);

    const int SMEM_W = (2560 + 5120) * 2 * 4;   // 61440 bytes
    cudaFuncSetAttribute(proj3_gemm, cudaFuncAttributeMaxDynamicSharedMemorySize, SMEM_W);
    cudaFuncSetAttribute(out_gemm,   cudaFuncAttributeMaxDynamicSharedMemorySize, SMEM_W);

    proj3_gemm<<<dim3(4, 32, 3), 256, SMEM_W>>>(Q, K, V, Wq, Wk, Wv, Qp, Kp, Vp);
    wo_permute<<<1024, 256>>>(Wo);

    tc_qrel<<<dim3(3, 8, 32), 256>>>(rel);
    tc_score<<<dim3(5, 8, 32), 256>>>(pad);
    tc_pv<<<dim3(8, 32), 256>>>();

    out_gemm<<<dim3(4, 32), 256, SMEM_W>>>(ctx, Wop, out);
}